// round 11
// baseline (speedup 1.0000x reference)
#include <cuda_runtime.h>
#include <cuda_bf16.h>

// SAN Subtraction: out[n,c,k,l] = x[n,c,oh,ow] - x[n,c, refl(oh+i-3), refl(ow+j-3)]
//   x: [8, 64, 56, 56] fp32, K=7, stride=1, pad=3 (reflect, dilation=1)
//   out: [8, 64, 49, 3136] fp32  (H_out = W_out = 56)
//
// R10 = champion pinned (R2/R9: 55.4/55.5us ncu, reproducible to 0.2%).
//
// Converged — quantitative floor model: the chip-wide LTS cap (~6300 B/cyc,
// path-independent, so TMA == STG) is crossed TWICE per output byte
// (SM->L2 write-allocate 315 MB + L2->DRAM writeback ~260 MB/replay,
// ~55 MB staying dirty in the 126 MB L2). Measured: 575 MB / 55.5 us =
// 10.4 TB/s ~= 5800 B/cyc @ ~1.8 GHz NAT = the LTS ceiling. This single
// shared cap pins DRAM at ~59%, L2 ~47%, L1 ~56% in every profile. Stores
// cannot bypass L2; writeback volume is L2-capacity-bounded; output bytes
// are fixed => ~55.5 us is the architectural floor. R3-R8 probed TMA bulk
// stores, conflict-free LDS.128 tiles, 64/128/256-thr CTAs, occ 3-16/SM,
// streaming hints: all >= 56.0 us.
//
// Strategy: one CTA per (n,c) plane. Stage the 56x56 plane in SMEM (12.25 KB),
// so global memory sees ONLY the 315 MB write stream. Reflect indices
// computed arithmetically: refl(p) = min(|p-3|, 110-|p-3|). Each thread owns
// float4-wide output positions; center + all reflected indices hoisted out
// of the fully unrolled 49-way k loop.

#define H 56
#define W 56
#define PLANE (H * W)       // 3136
#define KK 49
#define NPOS (H * (W / 4))  // 784 float4 positions per plane

__global__ __launch_bounds__(256, 4)
void san_subtraction_kernel(const float* __restrict__ x,
                            float* __restrict__ out,
                            int planes) {
    __shared__ float sp[PLANE];

    const int plane = blockIdx.x;
    const float* xin = x + (size_t)plane * PLANE;

    // Stage the input plane: 784 float4 coalesced loads.
    for (int t = threadIdx.x; t < NPOS; t += blockDim.x) {
        reinterpret_cast<float4*>(sp)[t] =
            reinterpret_cast<const float4*>(xin)[t];
    }
    __syncthreads();

    float* obase = out + (size_t)plane * KK * PLANE;

    for (int pos = threadIdx.x; pos < NPOS; pos += blockDim.x) {
        const int oh = pos / 14;
        const int w0 = (pos % 14) * 4;

        // Center (aligned float4 in smem).
        const float4 c = *reinterpret_cast<const float4*>(&sp[oh * W + w0]);

        // Reflected row byte-offsets for the 7 kernel rows.
        int rr[7];
#pragma unroll
        for (int i = 0; i < 7; ++i) {
            int p = oh + i - 3;
            p = p < 0 ? -p : p;                 // abs
            p = p < 110 - p ? p : 110 - p;      // mirror top edge (110 = 2*(H-1))
            rr[i] = p * W;
        }

        // Reflected column indices for the 7 kernel cols x 4 lanes.
        int cc[7][4];
#pragma unroll
        for (int j = 0; j < 7; ++j) {
#pragma unroll
            for (int q = 0; q < 4; ++q) {
                int p = w0 + q + j - 3;
                p = p < 0 ? -p : p;
                p = p < 110 - p ? p : 110 - p;
                cc[j][q] = p;
            }
        }

        float* o = obase + pos * 4;
#pragma unroll
        for (int i = 0; i < 7; ++i) {
            const float* row = sp + rr[i];
#pragma unroll
            for (int j = 0; j < 7; ++j) {
                float4 v;
                v.x = c.x - row[cc[j][0]];
                v.y = c.y - row[cc[j][1]];
                v.z = c.z - row[cc[j][2]];
                v.w = c.w - row[cc[j][3]];
                // Warp lanes have consecutive pos at the same (i,j):
                // each STG.128 group writes 512 contiguous bytes.
                *reinterpret_cast<float4*>(o + (i * 7 + j) * PLANE) = v;
            }
        }
    }
}

extern "C" void kernel_launch(void* const* d_in, const int* in_sizes, int n_in,
                              void* d_out, int out_size) {
    const float* x = (const float*)d_in[0];
    float* out = (float*)d_out;

    const int planes = in_sizes[0] / PLANE;  // N*C = 512
    san_subtraction_kernel<<<planes, 256>>>(x, out, planes);
}

// round 13
// speedup vs baseline: 1.0342x; 1.0342x over previous
#include <cuda_runtime.h>
#include <cuda_bf16.h>

// SAN Subtraction: out[n,c,k,l] = x[n,c,oh,ow] - x[n,c, refl(oh+i-3), refl(ow+j-3)]
//   x: [8, 64, 56, 56] fp32, K=7, stride=1, pad=3 (reflect)
//   out: [8, 64, 49, 3136] fp32
//
// R12 = R11 resubmitted verbatim (R11 hit an infra failure — container died
// before any bench; the write-through hypothesis is still unmeasured).
//
// Hypothesis: converged floor model says each output byte crosses the LTS
// interface twice (SM->L2 write-allocate + later L2->DRAM writeback);
// 575-630 MB over the ~6300 B/cyc path-independent LTS cap = the measured
// ~55.5us floor. Every probed store flavor (STG, __stcs, TMA bulk)
// allocates-then-writes-back. st.global.wt writes through immediately and
// leaves the line clean -> no deferred writeback -> potentially ONE LTS
// crossing. If the cap is on total LTS bandwidth, floor drops toward ~30us.
// If WT degenerates to allocate+drain, neutral -> revert to pinned champion
// (R2/R9: 55.4/55.5us ncu, reproducible).
//
// Register risk (R3 lesson: __stcs pushed a fatter loop over the 64-reg cap
// and spilled): applied here to the champion's 62-reg loop, 2 regs headroom,
// same __launch_bounds__(256,4).

#define H 56
#define W 56
#define PLANE (H * W)       // 3136
#define KK 49
#define NPOS (H * (W / 4))  // 784 float4 positions per plane

__global__ __launch_bounds__(256, 4)
void san_subtraction_kernel(const float* __restrict__ x,
                            float* __restrict__ out,
                            int planes) {
    __shared__ float sp[PLANE];

    const int plane = blockIdx.x;
    const float* xin = x + (size_t)plane * PLANE;

    // Stage the input plane: 784 float4 coalesced loads.
    for (int t = threadIdx.x; t < NPOS; t += blockDim.x) {
        reinterpret_cast<float4*>(sp)[t] =
            reinterpret_cast<const float4*>(xin)[t];
    }
    __syncthreads();

    float* obase = out + (size_t)plane * KK * PLANE;

    for (int pos = threadIdx.x; pos < NPOS; pos += blockDim.x) {
        const int oh = pos / 14;
        const int w0 = (pos % 14) * 4;

        // Center (aligned float4 in smem).
        const float4 c = *reinterpret_cast<const float4*>(&sp[oh * W + w0]);

        // Reflected row offsets for the 7 kernel rows.
        int rr[7];
#pragma unroll
        for (int i = 0; i < 7; ++i) {
            int p = oh + i - 3;
            p = p < 0 ? -p : p;                 // abs
            p = p < 110 - p ? p : 110 - p;      // mirror (110 = 2*(H-1))
            rr[i] = p * W;
        }

        // Reflected column indices for the 7 kernel cols x 4 lanes.
        int cc[7][4];
#pragma unroll
        for (int j = 0; j < 7; ++j) {
#pragma unroll
            for (int q = 0; q < 4; ++q) {
                int p = w0 + q + j - 3;
                p = p < 0 ? -p : p;
                p = p < 110 - p ? p : 110 - p;
                cc[j][q] = p;
            }
        }

        float* o = obase + pos * 4;
#pragma unroll
        for (int i = 0; i < 7; ++i) {
            const float* row = sp + rr[i];
#pragma unroll
            for (int j = 0; j < 7; ++j) {
                float4 v;
                v.x = c.x - row[cc[j][0]];
                v.y = c.y - row[cc[j][1]];
                v.z = c.z - row[cc[j][2]];
                v.w = c.w - row[cc[j][3]];
                // Write-through STG.128: immediate DRAM write, clean line,
                // no deferred L2 writeback. Lanes consecutive at fixed
                // (i,j): 512 B contiguous full-line warp stores.
                __stwt(reinterpret_cast<float4*>(o + (i * 7 + j) * PLANE), v);
            }
        }
    }
}

extern "C" void kernel_launch(void* const* d_in, const int* in_sizes, int n_in,
                              void* d_out, int out_size) {
    const float* x = (const float*)d_in[0];
    float* out = (float*)d_out;

    const int planes = in_sizes[0] / PLANE;  // N*C = 512
    san_subtraction_kernel<<<planes, 256>>>(x, out, planes);
}